// round 11
// baseline (speedup 1.0000x reference)
#include <cuda_runtime.h>
#include <math.h>
#include <stdint.h>

// ---------------- problem constants ----------------
#define NTOK   4096      // QLEN*B
#define RTOK   8192      // RLEN*B
#define DMODEL 1024
#define NHEAD  16
#define DHEAD  64
#define DFF    4096

// ---------------- scratch (__device__ globals; allocation-free) ----------------
__device__ float g_qkv [3 * 4096 * 1024];  // contiguous q|k|v
__device__ float g_kr  [8192 * 1024];
__device__ float g_ef  [4096 * 16 * 2];
__device__ float g_sg  [4096];             // d[i*4+b] = (seg_i != seg_0)
__device__ float g_av  [4096 * 1024];
__device__ float g_pre [4096 * 1024];
__device__ float g_o1  [4096 * 1024];
__device__ float g_ffh [4096 * 4096];
__device__ float g_p2  [4096 * 1024];
// tf32-pre-rounded operands (numerically identical to per-load cvt)
__device__ float g_ht  [4096 * 1024];
__device__ float g_wqkv[3 * 1024 * 1024];  // contiguous q_w|k_w|v_w rounded
__device__ float g_wo  [1024 * 1024];
__device__ float g_wr  [1024 * 1024];
__device__ float g_w1t [1024 * 4096];
__device__ float g_w2t [4096 * 1024];

__device__ __forceinline__ float gelu_exact(float x) {
    return 0.5f * x * (1.0f + erff(x * 0.70710678118654752f));
}
__device__ __forceinline__ uint32_t f2tf32(float x) {
    uint32_t u; asm("cvt.rna.tf32.f32 %0, %1;" : "=r"(u) : "f"(x)); return u;
}
__device__ __forceinline__ float round_tf32f(float x) { return __uint_as_float(f2tf32(x)); }

__device__ __forceinline__ void mma_tf32(float* c, const uint32_t* a, const uint32_t* b) {
    asm volatile(
        "mma.sync.aligned.m16n8k8.row.col.f32.tf32.tf32.f32 "
        "{%0,%1,%2,%3}, {%4,%5,%6,%7}, {%8,%9}, {%0,%1,%2,%3};\n"
        : "+f"(c[0]), "+f"(c[1]), "+f"(c[2]), "+f"(c[3])
        : "r"(a[0]), "r"(a[1]), "r"(a[2]), "r"(a[3]), "r"(b[0]), "r"(b[1]));
}
__device__ __forceinline__ void cp_async16(float* s, const float* g) {
    uint32_t sa = (uint32_t)__cvta_generic_to_shared(s);
    asm volatile("cp.async.cg.shared.global [%0], [%1], 16;" :: "r"(sa), "l"(g));
}
__device__ __forceinline__ void cp_commit() { asm volatile("cp.async.commit_group;"); }
template<int N> __device__ __forceinline__ void cp_wait() {
    asm volatile("cp.async.wait_group %0;" :: "n"(N));
}

// ---------------- elementwise tf32 rounding passes ----------------
__global__ void round_kernel(const float4* __restrict__ src, float4* __restrict__ dst, int n4)
{
    int i = blockIdx.x * 256 + threadIdx.x;
    if (i < n4) {
        float4 v = src[i];
        v.x = round_tf32f(v.x); v.y = round_tf32f(v.y);
        v.z = round_tf32f(v.z); v.w = round_tf32f(v.w);
        dst[i] = v;
    }
}
__global__ void round3_kernel(const float4* __restrict__ s0, const float4* __restrict__ s1,
                              const float4* __restrict__ s2, float4* __restrict__ dst, int n4per)
{
    int i = blockIdx.x * 256 + threadIdx.x;
    if (i < 3 * n4per) {
        const float4* s = (i < n4per) ? s0 : (i < 2 * n4per ? s1 : s2);
        int idx = i - (i < n4per ? 0 : (i < 2 * n4per ? n4per : 2 * n4per));
        float4 v = s[idx];
        v.x = round_tf32f(v.x); v.y = round_tf32f(v.y);
        v.z = round_tf32f(v.z); v.w = round_tf32f(v.w);
        dst[i] = v;
    }
}

// ---------------- segment vector extraction ----------------
__global__ void seg_kernel(const float* __restrict__ segm, float* __restrict__ d)
{
    int t = blockIdx.x * 256 + threadIdx.x;
    if (t < 4096) {
        int i = t >> 2, b = t & 3;
        d[t] = segm[(long long)i * 8192 + b * 2 + 1];
    }
}

// ---------------- tf32 tensor-core GEMM, 3-stage cp.async ----------------
template<int BM, int BN, int WGM, int WGN, bool TRANSB, int EPI, bool CVTA, bool CVTB, bool RND>
__global__ __launch_bounds__(WGM * WGN * 32, 2)
void gemm_tc(const float* __restrict__ A, const float* __restrict__ B,
             float* __restrict__ C, const float* __restrict__ bias,
             const float* __restrict__ R,
             int M, int N, int K, int lda, int ldb, int ldc, int ldr,
             long long sAb, long long sAn, long long sBb, long long sBn,
             long long sCb, long long sCn, int causal)
{
    constexpr int BK = 32;
    constexpr int THREADS = WGM * WGN * 32;
    constexpr int WTM = BM / WGM, WTN = BN / WGN;
    constexpr int MT = WTM / 16, NT = WTN / 8;
    constexpr int LDA_S = BK + 4;
    constexpr int ASZ = BM * LDA_S;
    constexpr int BSZ = TRANSB ? BN * (BK + 4) : BK * (BN + 4);
    constexpr int NLA = BM * BK / (4 * THREADS);
    constexpr int NLB = BN * BK / (4 * THREADS);
    constexpr int BNQ = BN / 4;

    extern __shared__ float sm[];
    float* Abase = sm;
    float* Bbase = sm + 3 * ASZ;

    const int tid  = threadIdx.x;
    const int lane = tid & 31;
    const int warp = tid >> 5;
    const int wm = warp / WGN, wn = warp % WGN;

    const int zb = blockIdx.z >> 4, zn = blockIdx.z & 15;
    const float* Ap = A + zb * sAb + zn * sAn;
    const float* Bp = B + zb * sBb + zn * sBn;
    float*       Cp = C + zb * sCb + zn * sCn;

    const int row0 = blockIdx.y * BM;
    const int col0 = blockIdx.x * BN;
    const int kEnd = causal ? ((row0 + BM < K) ? (row0 + BM) : K) : K;

    float acc[MT][NT][4];
    #pragma unroll
    for (int mt = 0; mt < MT; mt++)
        #pragma unroll
        for (int nt = 0; nt < NT; nt++)
            #pragma unroll
            for (int q = 0; q < 4; q++) acc[mt][nt][q] = 0.0f;

    auto loadAB = [&](int kt, int stage) {
        float* As = Abase + stage * ASZ;
        #pragma unroll
        for (int it = 0; it < NLA; it++) {
            int idx = it * THREADS + tid;
            int rm = idx >> 3, kq = (idx & 7) << 2;
            cp_async16(As + rm * LDA_S + kq,
                       Ap + (long long)(row0 + rm) * lda + kt + kq);
        }
        float* Bs = Bbase + stage * BSZ;
        if (!TRANSB) {
            #pragma unroll
            for (int it = 0; it < NLB; it++) {
                int idx = it * THREADS + tid;
                int kk = idx / BNQ, nq = (idx % BNQ) << 2;
                cp_async16(Bs + kk * (BN + 4) + nq,
                           Bp + (long long)(kt + kk) * ldb + col0 + nq);
            }
        } else {
            #pragma unroll
            for (int it = 0; it < NLB; it++) {
                int idx = it * THREADS + tid;
                int nn = idx >> 3, kq = (idx & 7) << 2;
                cp_async16(Bs + nn * (BK + 4) + kq,
                           Bp + (long long)(col0 + nn) * ldb + kt + kq);
            }
        }
        cp_commit();
    };

    const int ntile = kEnd / BK;
    loadAB(0, 0);
    if (ntile > 1) loadAB(BK, 1);

    for (int i = 0; i < ntile; i++) {
        if (i + 1 < ntile) cp_wait<1>();
        else               cp_wait<0>();
        __syncthreads();

        if (i + 2 < ntile) loadAB((i + 2) * BK, (i + 2) % 3);

        const float* As = Abase + (i % 3) * ASZ;
        const float* Bs = Bbase + (i % 3) * BSZ;

        #pragma unroll
        for (int ks = 0; ks < 4; ks++) {
            const int kc = ks * 8 + (lane & 3);
            uint32_t aF[MT][4];
            const int ar = wm * WTM + (lane >> 2);
            #pragma unroll
            for (int mt = 0; mt < MT; mt++) {
                const float* ap = As + (ar + mt * 16) * LDA_S;
                if (CVTA) {
                    aF[mt][0] = f2tf32(ap[kc]);
                    aF[mt][1] = f2tf32(ap[8 * LDA_S + kc]);
                    aF[mt][2] = f2tf32(ap[kc + 4]);
                    aF[mt][3] = f2tf32(ap[8 * LDA_S + kc + 4]);
                } else {
                    aF[mt][0] = __float_as_uint(ap[kc]);
                    aF[mt][1] = __float_as_uint(ap[8 * LDA_S + kc]);
                    aF[mt][2] = __float_as_uint(ap[kc + 4]);
                    aF[mt][3] = __float_as_uint(ap[8 * LDA_S + kc + 4]);
                }
            }
            uint32_t bF[NT][2];
            const int c0 = wn * WTN + (lane >> 2);
            if (!TRANSB) {
                #pragma unroll
                for (int nt = 0; nt < NT; nt++) {
                    float b0 = Bs[kc * (BN + 4) + c0 + nt * 8];
                    float b1 = Bs[(kc + 4) * (BN + 4) + c0 + nt * 8];
                    bF[nt][0] = CVTB ? f2tf32(b0) : __float_as_uint(b0);
                    bF[nt][1] = CVTB ? f2tf32(b1) : __float_as_uint(b1);
                }
            } else {
                #pragma unroll
                for (int nt = 0; nt < NT; nt++) {
                    const float* bp = Bs + (c0 + nt * 8) * (BK + 4);
                    bF[nt][0] = CVTB ? f2tf32(bp[kc]) : __float_as_uint(bp[kc]);
                    bF[nt][1] = CVTB ? f2tf32(bp[kc + 4]) : __float_as_uint(bp[kc + 4]);
                }
            }
            #pragma unroll
            for (int mt = 0; mt < MT; mt++)
                #pragma unroll
                for (int nt = 0; nt < NT; nt++)
                    mma_tf32(acc[mt][nt], aF[mt], bF[nt]);
        }
    }

    #pragma unroll
    for (int mt = 0; mt < MT; mt++) {
        int rbase = row0 + wm * WTM + mt * 16 + (lane >> 2);
        #pragma unroll
        for (int nt = 0; nt < NT; nt++) {
            int c = col0 + wn * WTN + nt * 8 + (lane & 3) * 2;
            #pragma unroll
            for (int h2 = 0; h2 < 2; h2++) {
                int rr = rbase + h2 * 8;
                if (rr < M && c + 1 < N) {
                    float v0 = acc[mt][nt][h2 * 2];
                    float v1 = acc[mt][nt][h2 * 2 + 1];
                    if (EPI == 1) {
                        v0 = gelu_exact(v0 + bias[c]);
                        v1 = gelu_exact(v1 + bias[c + 1]);
                    }
                    if (EPI == 2) {
                        const float* rp = R + (long long)rr * ldr + c;
                        v0 += rp[0]; v1 += rp[1];
                    }
                    if (EPI == 3) {
                        const float* rp = R + (long long)rr * ldr + c;
                        v0 += bias[c] + rp[0]; v1 += bias[c + 1] + rp[1];
                    }
                    if (RND) { v0 = round_tf32f(v0); v1 = round_tf32f(v1); }
                    float2 o; o.x = v0; o.y = v1;
                    *(float2*)(Cp + (long long)rr * ldc + c) = o;
                }
            }
        }
    }
}

constexpr int gemm_smem(int BM, int BN, bool TRANSB) {
    return (3 * BM * 36 + 3 * (TRANSB ? BN * 36 : 32 * (BN + 4))) * 4;
}

// ---------------- ef precompute ----------------
__global__ void ef_kernel(const float* __restrict__ q, const float* __restrict__ rsb,
                          const float* __restrict__ se, float* __restrict__ ef)
{
    const int pair = blockIdx.x * 8 + (threadIdx.x >> 5);
    const int lane = threadIdx.x & 31;
    const int t = pair >> 4, n = pair & 15;
    const float* qp = q + (long long)t * 1024 + n * 64;
    float e0 = 0.f, e1 = 0.f;
    #pragma unroll
    for (int d = lane; d < 64; d += 32) {
        float qv = qp[d] + rsb[n * 64 + d];
        e0 += qv * se[n * 64 + d];
        e1 += qv * se[1024 + n * 64 + d];
    }
    #pragma unroll
    for (int o = 16; o; o >>= 1) {
        e0 += __shfl_xor_sync(0xffffffffu, e0, o);
        e1 += __shfl_xor_sync(0xffffffffu, e1, o);
    }
    if (lane == 0) {
        ef[((long long)t * 16 + n) * 2]     = e0;
        ef[((long long)t * 16 + n) * 2 + 1] = e1;
    }
}

// ---------------- FLASH: fused score + online softmax + P.V ----------------
// One block = 64 q-rows (i-tile) for one (b,n). Loops over causal j-tiles.
// Score core identical to the verified score_kernel; softmax online per row
// (16-lane shfl groups); PV via SIMT FMA on smem-staged P (row-major) and V.
// Output av tf32-rounded (consumed by o-proj with CVTA=false).
static const int FL_SMEM = (4 * 64 * 68 + 64 * 132 + 5 * 64) * 4;  // 104704 B

__global__ __launch_bounds__(256, 2)
void flash_kernel(const float* __restrict__ q, const float* __restrict__ k,
                  const float* __restrict__ kr, const float* __restrict__ v,
                  const float* __restrict__ rwb, const float* __restrict__ rrb,
                  const float* __restrict__ ef, const float* __restrict__ dseg,
                  float* __restrict__ av)
{
    const int it = 15 - blockIdx.x;          // heavy i-tiles first
    const int i0 = it * 64;
    const int z = blockIdx.y, b = z >> 4, n = z & 15;
    const int tid = threadIdx.x;

    extern __shared__ float sm[];
    float* Qt   = sm;                 // [64 d][68] q + r_w_bias, d-major
    float* Kt   = Qt + 64 * 68;       // [64 d][68]
    float* Krt  = Kt + 64 * 68;       // [64 d][132] halo
    float* Vt   = Krt + 64 * 132;     // [64 j][68] j-major
    float* Pt   = Vt + 64 * 68;       // [64 row][68] row-major probs
    float* dbs  = Pt + 64 * 68;       // [64]
    float* efs0 = dbs + 64;
    float* efs1 = efs0 + 64;
    float* dsi  = efs1 + 64;
    float* dsj  = dsi + 64;

    const float* qb  = q  + b * 1024 + n * 64;
    const float* kb  = k  + b * 1024 + n * 64;
    const float* krb = kr + b * 1024 + n * 64;
    const float* vb  = v  + b * 1024 + n * 64;

    // one-time loads
    for (int e = tid; e < 4096; e += 256) {
        int row = e >> 6, d = e & 63;
        Qt[d * 68 + row] = qb[(long long)(i0 + row) * 4096 + d] + rwb[n * 64 + d];
    }
    if (tid < 64) {
        dbs[tid] = rrb[n * 64 + tid] - rwb[n * 64 + tid];
        int t = (i0 + tid) * 4 + b;
        efs0[tid] = ef[((long long)t * 16 + n) * 2];
        efs1[tid] = ef[((long long)t * 16 + n) * 2 + 1];
        dsi[tid]  = dseg[t];
    }

    const int tx = tid & 15, ty = tid >> 4;
    const int ib = ty * 4, jb = tx * 4;
    const int r0 = jb - ib + 60;

    float m[4], l[4], acc[4][4];
    #pragma unroll
    for (int a = 0; a < 4; a++) {
        m[a] = -3.4e38f; l[a] = 0.f;
        #pragma unroll
        for (int c = 0; c < 4; c++) acc[a][c] = 0.f;
    }

    for (int jt = 0; jt <= it; jt++) {
        const int j0 = jt * 64;
        __syncthreads();   // previous-iteration readers done (also pre-first no-op)

        for (int e = tid; e < 4096; e += 256) {
            int row = e >> 6, d = e & 63;
            Kt[d * 68 + row] = kb[(long long)(j0 + row) * 4096 + d];
            Vt[row * 68 + d] = vb[(long long)(j0 + row) * 4096 + d];
        }
        const int rel0 = j0 - i0 + 1024 - 63;
        for (int e = tid; e < 127 * 64; e += 256) {
            int row = e >> 6, d = e & 63;
            Krt[d * 132 + row] = krb[(long long)(rel0 + row) * 4096 + d];
        }
        if (tid < 64) dsj[tid] = dseg[(j0 + tid) * 4 + b];
        __syncthreads();

        // ---- score tile (verified core) ----
        float ac[4][4] = {}, bd[4][4] = {};
        #pragma unroll 4
        for (int kk = 0; kk < 64; kk++) {
            float db = dbs[kk];
            float qa[4], kv[4], krv[7];
            #pragma unroll
            for (int a = 0; a < 4; a++) qa[a] = Qt[kk * 68 + ib + a];
            #pragma unroll
            for (int c = 0; c < 4; c++) kv[c] = Kt[kk * 68 + jb + c];
            #pragma unroll
            for (int mm = 0; mm < 7; mm++) krv[mm] = Krt[kk * 132 + r0 + mm];
            #pragma unroll
            for (int a = 0; a < 4; a++) {
                float qd = qa[a] + db;
                #pragma unroll
                for (int c = 0; c < 4; c++) {
                    ac[a][c] += qa[a] * kv[c];
                    bd[a][c] += qd * krv[c - a + 3];
                }
            }
        }

        const bool diag = (jt == it);
        float sc[4][4];
        #pragma unroll
        for (int a = 0; a < 4; a++) {
            float e0 = efs0[ib + a], e1 = efs1[ib + a];
            float di = dsi[ib + a];
            #pragma unroll
            for (int c = 0; c < 4; c++) {
                float e = (dsj[jb + c] != di) ? e1 : e0;
                float val = (ac[a][c] + bd[a][c] + e) * 0.125f;
                if (diag && (jb + c > ib + a)) val = -1e30f;
                sc[a][c] = val;
            }
        }

        // ---- online softmax (per row, 16-lane tx groups) ----
        #pragma unroll
        for (int a = 0; a < 4; a++) {
            float tmax = fmaxf(fmaxf(sc[a][0], sc[a][1]), fmaxf(sc[a][2], sc[a][3]));
            #pragma unroll
            for (int o = 8; o; o >>= 1) tmax = fmaxf(tmax, __shfl_xor_sync(0xffffffffu, tmax, o));
            float mn = fmaxf(m[a], tmax);
            float alpha = expf(m[a] - mn);
            float p0 = expf(sc[a][0] - mn), p1 = expf(sc[a][1] - mn);
            float p2 = expf(sc[a][2] - mn), p3 = expf(sc[a][3] - mn);
            float rsum = p0 + p1 + p2 + p3;
            #pragma unroll
            for (int o = 8; o; o >>= 1) rsum += __shfl_xor_sync(0xffffffffu, rsum, o);
            l[a] = l[a] * alpha + rsum;
            m[a] = mn;
            #pragma unroll
            for (int c = 0; c < 4; c++) acc[a][c] *= alpha;
            float* pr = Pt + (ib + a) * 68 + jb;
            pr[0] = p0; pr[1] = p1; pr[2] = p2; pr[3] = p3;
        }
        __syncthreads();

        // ---- PV accumulate: acc[row][d] += P[row][j] * V[j][d] ----
        #pragma unroll 4
        for (int kk = 0; kk < 64; kk++) {
            float pa[4], vv[4];
            #pragma unroll
            for (int a = 0; a < 4; a++) pa[a] = Pt[(ib + a) * 68 + kk];
            #pragma unroll
            for (int c = 0; c < 4; c++) vv[c] = Vt[kk * 68 + jb + c];
            #pragma unroll
            for (int a = 0; a < 4; a++)
                #pragma unroll
                for (int c = 0; c < 4; c++)
                    acc[a][c] += pa[a] * vv[c];
        }
    }

    // ---- epilogue: normalize, round, store ----
    #pragma unroll
    for (int a = 0; a < 4; a++) {
        float inv = 1.0f / l[a];
        float4 o;
        o.x = round_tf32f(acc[a][0] * inv);
        o.y = round_tf32f(acc[a][1] * inv);
        o.z = round_tf32f(acc[a][2] * inv);
        o.w = round_tf32f(acc[a][3] * inv);
        long long off = ((long long)(i0 + ib + a) * 4 + b) * 1024 + n * 64 + jb;
        *(float4*)(av + off) = o;
    }
}

// ---------------- layernorm ----------------
__global__ void ln_kernel(const float* __restrict__ X, const float* __restrict__ gw,
                          const float* __restrict__ bw, float* __restrict__ Y)
{
    __shared__ float red[8];
    __shared__ float stat[2];
    const int row = blockIdx.x;
    const int tid = threadIdx.x;
    const int lane = tid & 31, wid = tid >> 5;
    float4 x = ((const float4*)(X + (long long)row * 1024))[tid];

    float s = x.x + x.y + x.z + x.w;
    #pragma unroll
    for (int o = 16; o; o >>= 1) s += __shfl_xor_sync(0xffffffffu, s, o);
    if (lane == 0) red[wid] = s;
    __syncthreads();
    if (tid == 0) {
        float t = 0.f;
        for (int i = 0; i < 8; i++) t += red[i];
        stat[0] = t * (1.0f / 1024.0f);
    }
    __syncthreads();
    float mu = stat[0];
    float d0 = x.x - mu, d1 = x.y - mu, d2 = x.z - mu, d3 = x.w - mu;
    float sq = d0 * d0 + d1 * d1 + d2 * d2 + d3 * d3;
    #pragma unroll
    for (int o = 16; o; o >>= 1) sq += __shfl_xor_sync(0xffffffffu, sq, o);
    if (lane == 0) red[wid] = sq;
    __syncthreads();
    if (tid == 0) {
        float t = 0.f;
        for (int i = 0; i < 8; i++) t += red[i];
        stat[1] = rsqrtf(t * (1.0f / 1024.0f) + 1e-12f);
    }
    __syncthreads();
    float rs = stat[1];
    float4 g4 = ((const float4*)gw)[tid];
    float4 b4 = ((const float4*)bw)[tid];
    float4 y;
    y.x = d0 * rs * g4.x + b4.x;
    y.y = d1 * rs * g4.y + b4.y;
    y.z = d2 * rs * g4.z + b4.z;
    y.w = d3 * rs * g4.w + b4.w;
    ((float4*)(Y + (long long)row * 1024))[tid] = y;
}

// ---------------- orchestration ----------------
extern "C" void kernel_launch(void* const* d_in, const int* in_sizes, int n_in,
                              void* d_out, int out_size)
{
    (void)in_sizes; (void)n_in; (void)out_size;
    const float* h    = (const float*)d_in[0];
    const float* r    = (const float*)d_in[1];
    const float* segm = (const float*)d_in[3];
    const float* q_w  = (const float*)d_in[4];
    const float* k_w  = (const float*)d_in[5];
    const float* v_w  = (const float*)d_in[6];
    const float* o_w  = (const float*)d_in[7];
    const float* r_w  = (const float*)d_in[8];
    const float* rrb  = (const float*)d_in[9];
    const float* rsb  = (const float*)d_in[10];
    const float* rwb  = (const float*)d_in[11];
    const float* se   = (const float*)d_in[12];
    const float* ln1g = (const float*)d_in[13];
    const float* ln1b = (const float*)d_in[14];
    const float* w1   = (const float*)d_in[15];
    const float* b1   = (const float*)d_in[16];
    const float* w2   = (const float*)d_in[17];
    const float* b2   = (const float*)d_in[18];
    const float* ln2g = (const float*)d_in[19];
    const float* ln2b = (const float*)d_in[20];
    float* out = (float*)d_out;

    float *gqkv, *gkr, *gef, *gsg, *gav, *gpre, *go1, *gffh, *gp2;
    float *ght, *gwqkv, *gwo, *gwr, *gw1t, *gw2t;
    cudaGetSymbolAddress((void**)&gqkv, g_qkv);
    cudaGetSymbolAddress((void**)&gkr,  g_kr);
    cudaGetSymbolAddress((void**)&gef,  g_ef);
    cudaGetSymbolAddress((void**)&gsg,  g_sg);
    cudaGetSymbolAddress((void**)&gav,  g_av);
    cudaGetSymbolAddress((void**)&gpre, g_pre);
    cudaGetSymbolAddress((void**)&go1,  g_o1);
    cudaGetSymbolAddress((void**)&gffh, g_ffh);
    cudaGetSymbolAddress((void**)&gp2,  g_p2);
    cudaGetSymbolAddress((void**)&ght,  g_ht);
    cudaGetSymbolAddress((void**)&gwqkv, g_wqkv);
    cudaGetSymbolAddress((void**)&gwo,  g_wo);
    cudaGetSymbolAddress((void**)&gwr,  g_wr);
    cudaGetSymbolAddress((void**)&gw1t, g_w1t);
    cudaGetSymbolAddress((void**)&gw2t, g_w2t);

    float* gq = gqkv;
    float* gk = gqkv + 4194304;
    float* gv = gqkv + 8388608;

    const int SM_NRM = gemm_smem(128, 128, false);
    const int SM_TRB = gemm_smem(128, 128, true);

    cudaFuncSetAttribute(flash_kernel, cudaFuncAttributeMaxDynamicSharedMemorySize, FL_SMEM);
    cudaFuncSetAttribute((const void*)gemm_tc<128,128,4,2,false,0,false,false,false>,
                         cudaFuncAttributeMaxDynamicSharedMemorySize, SM_NRM);
    cudaFuncSetAttribute((const void*)gemm_tc<128,128,4,2,true,2,false,false,false>,
                         cudaFuncAttributeMaxDynamicSharedMemorySize, SM_TRB);
    cudaFuncSetAttribute((const void*)gemm_tc<128,128,4,2,false,1,true,false,true>,
                         cudaFuncAttributeMaxDynamicSharedMemorySize, SM_NRM);
    cudaFuncSetAttribute((const void*)gemm_tc<128,128,4,2,false,3,false,false,false>,
                         cudaFuncAttributeMaxDynamicSharedMemorySize, SM_NRM);

    // pre-round pure GEMM operands to tf32
    round_kernel<<<4096,256>>>((const float4*)h,   (float4*)ght,  4194304/4);
    round3_kernel<<<3072,256>>>((const float4*)q_w, (const float4*)k_w, (const float4*)v_w,
                                (float4*)gwqkv, 1048576/4);
    round_kernel<<<1024,256>>>((const float4*)o_w, (float4*)gwo,  1048576/4);
    round_kernel<<<1024,256>>>((const float4*)r_w, (float4*)gwr,  1048576/4);
    round_kernel<<<4096,256>>>((const float4*)w1,  (float4*)gw1t, 4194304/4);
    round_kernel<<<4096,256>>>((const float4*)w2,  (float4*)gw2t, 4194304/4);
    seg_kernel<<<16,256>>>(segm, gsg);

    // q/k/v projections: one batched launch
    gemm_tc<128,128,4,2,false,0,false,false,false><<<dim3(8,32,3),256,SM_NRM>>>(ght, gwqkv, gqkv,
        nullptr, nullptr, NTOK, DMODEL, DMODEL, 1024,1024,1024,0,
        0, 0, 0, 1048576ll, 0, 4194304ll, 0);
    // relative projection: only rel rows <= 1087 are read
    gemm_tc<128,128,4,2,false,0,false,false,false><<<dim3(8,34,1),256,SM_NRM>>>(r, gwr, gkr,
        nullptr, nullptr, RTOK, DMODEL, DMODEL, 1024,1024,1024,0, 0,0,0,0,0,0, 0);

    ef_kernel<<<8192,256>>>(gq, rsb, se, gef);

    // fused score + softmax + PV -> attn_vec (tf32-rounded)
    flash_kernel<<<dim3(16,64),256,FL_SMEM>>>(gq, gk, gkr, gv, rwb, rrb, gef, gsg, gav);

    // o-projection + residual h
    gemm_tc<128,128,4,2,true,2,false,false,false><<<dim3(8,32,1),256,SM_TRB>>>(gav, gwo, gpre,
        nullptr, h, NTOK, DMODEL, DMODEL, 1024,1024,1024,1024, 0,0,0,0,0,0, 0);
    ln_kernel<<<4096,256>>>(gpre, ln1g, ln1b, go1);

    // FF1 (+bias, GELU) and FF2 (+bias, +residual)
    gemm_tc<128,128,4,2,false,1,true,false,true><<<dim3(32,32,1),256,SM_NRM>>>(go1, gw1t, gffh,
        b1, nullptr, NTOK, DFF, DMODEL, 1024,4096,4096,0, 0,0,0,0,0,0, 0);
    gemm_tc<128,128,4,2,false,3,false,false,false><<<dim3(8,32,1),256,SM_NRM>>>(gffh, gw2t, gp2,
        b2, go1, NTOK, DMODEL, DFF, 4096,1024,1024,1024, 0,0,0,0,0,0, 0);
    ln_kernel<<<4096,256>>>(gp2, ln2g, ln2b, out);
}

// round 12
// speedup vs baseline: 1.0147x; 1.0147x over previous
#include <cuda_runtime.h>
#include <math.h>
#include <stdint.h>

// ---------------- problem constants ----------------
#define NTOK   4096      // QLEN*B
#define RTOK   8192      // RLEN*B
#define DMODEL 1024
#define NHEAD  16
#define DHEAD  64
#define DFF    4096

// ---------------- scratch (__device__ globals; allocation-free) ----------------
__device__ float g_qkv [3 * 4096 * 1024];  // contiguous q|k|v
__device__ float g_kr  [8192 * 1024];
__device__ float g_ef  [4096 * 16 * 2];
__device__ float g_sg  [4096];             // d[i*4+b] = (seg_i != seg_0)
__device__ float g_s   [67108864];         // scores->probs in place
__device__ float g_av  [4096 * 1024];
__device__ float g_pre [4096 * 1024];
__device__ float g_o1  [4096 * 1024];
__device__ float g_ffh [4096 * 4096];
__device__ float g_p2  [4096 * 1024];
// tf32-pre-rounded operands (numerically identical to per-load cvt)
__device__ float g_ht  [4096 * 1024];
__device__ float g_wqkv[3 * 1024 * 1024];  // contiguous q_w|k_w|v_w rounded
__device__ float g_wo  [1024 * 1024];
__device__ float g_wr  [1024 * 1024];
__device__ float g_w1t [1024 * 4096];
__device__ float g_w2t [4096 * 1024];

__device__ __forceinline__ float gelu_exact(float x) {
    return 0.5f * x * (1.0f + erff(x * 0.70710678118654752f));
}
__device__ __forceinline__ uint32_t f2tf32(float x) {
    uint32_t u; asm("cvt.rna.tf32.f32 %0, %1;" : "=r"(u) : "f"(x)); return u;
}
__device__ __forceinline__ float round_tf32f(float x) { return __uint_as_float(f2tf32(x)); }

__device__ __forceinline__ void mma_tf32(float* c, const uint32_t* a, const uint32_t* b) {
    asm volatile(
        "mma.sync.aligned.m16n8k8.row.col.f32.tf32.tf32.f32 "
        "{%0,%1,%2,%3}, {%4,%5,%6,%7}, {%8,%9}, {%0,%1,%2,%3};\n"
        : "+f"(c[0]), "+f"(c[1]), "+f"(c[2]), "+f"(c[3])
        : "r"(a[0]), "r"(a[1]), "r"(a[2]), "r"(a[3]), "r"(b[0]), "r"(b[1]));
}
__device__ __forceinline__ void cp_async16(float* s, const float* g) {
    uint32_t sa = (uint32_t)__cvta_generic_to_shared(s);
    asm volatile("cp.async.cg.shared.global [%0], [%1], 16;" :: "r"(sa), "l"(g));
}
__device__ __forceinline__ void cp_commit() { asm volatile("cp.async.commit_group;"); }
template<int N> __device__ __forceinline__ void cp_wait() {
    asm volatile("cp.async.wait_group %0;" :: "n"(N));
}

// ---------------- elementwise tf32 rounding passes ----------------
__global__ void round_kernel(const float4* __restrict__ src, float4* __restrict__ dst, int n4)
{
    int i = blockIdx.x * 256 + threadIdx.x;
    if (i < n4) {
        float4 v = src[i];
        v.x = round_tf32f(v.x); v.y = round_tf32f(v.y);
        v.z = round_tf32f(v.z); v.w = round_tf32f(v.w);
        dst[i] = v;
    }
}
__global__ void round3_kernel(const float4* __restrict__ s0, const float4* __restrict__ s1,
                              const float4* __restrict__ s2, float4* __restrict__ dst, int n4per)
{
    int i = blockIdx.x * 256 + threadIdx.x;
    if (i < 3 * n4per) {
        const float4* s = (i < n4per) ? s0 : (i < 2 * n4per ? s1 : s2);
        int idx = i - (i < n4per ? 0 : (i < 2 * n4per ? n4per : 2 * n4per));
        float4 v = s[idx];
        v.x = round_tf32f(v.x); v.y = round_tf32f(v.y);
        v.z = round_tf32f(v.z); v.w = round_tf32f(v.w);
        dst[i] = v;
    }
}

// ---------------- segment vector extraction ----------------
__global__ void seg_kernel(const float* __restrict__ segm, float* __restrict__ d)
{
    int t = blockIdx.x * 256 + threadIdx.x;
    if (t < 4096) {
        int i = t >> 2, b = t & 3;
        d[t] = segm[(long long)i * 8192 + b * 2 + 1];
    }
}

// ---------------- tf32 tensor-core GEMM, 3-stage cp.async ----------------
template<int BM, int BN, int WGM, int WGN, bool TRANSB, int EPI, bool CVTA, bool CVTB, bool RND>
__global__ __launch_bounds__(WGM * WGN * 32, 2)
void gemm_tc(const float* __restrict__ A, const float* __restrict__ B,
             float* __restrict__ C, const float* __restrict__ bias,
             const float* __restrict__ R,
             int M, int N, int K, int lda, int ldb, int ldc, int ldr,
             long long sAb, long long sAn, long long sBb, long long sBn,
             long long sCb, long long sCn, int causal)
{
    constexpr int BK = 32;
    constexpr int THREADS = WGM * WGN * 32;
    constexpr int WTM = BM / WGM, WTN = BN / WGN;
    constexpr int MT = WTM / 16, NT = WTN / 8;
    constexpr int LDA_S = BK + 4;
    constexpr int ASZ = BM * LDA_S;
    constexpr int BSZ = TRANSB ? BN * (BK + 4) : BK * (BN + 4);
    constexpr int NLA = BM * BK / (4 * THREADS);
    constexpr int NLB = BN * BK / (4 * THREADS);
    constexpr int BNQ = BN / 4;

    extern __shared__ float sm[];
    float* Abase = sm;
    float* Bbase = sm + 3 * ASZ;

    const int tid  = threadIdx.x;
    const int lane = tid & 31;
    const int warp = tid >> 5;
    const int wm = warp / WGN, wn = warp % WGN;

    const int zb = blockIdx.z >> 4, zn = blockIdx.z & 15;
    const float* Ap = A + zb * sAb + zn * sAn;
    const float* Bp = B + zb * sBb + zn * sBn;
    float*       Cp = C + zb * sCb + zn * sCn;

    const int row0 = blockIdx.y * BM;
    const int col0 = blockIdx.x * BN;
    const int kEnd = causal ? ((row0 + BM < K) ? (row0 + BM) : K) : K;

    float acc[MT][NT][4];
    #pragma unroll
    for (int mt = 0; mt < MT; mt++)
        #pragma unroll
        for (int nt = 0; nt < NT; nt++)
            #pragma unroll
            for (int q = 0; q < 4; q++) acc[mt][nt][q] = 0.0f;

    auto loadAB = [&](int kt, int stage) {
        float* As = Abase + stage * ASZ;
        #pragma unroll
        for (int it = 0; it < NLA; it++) {
            int idx = it * THREADS + tid;
            int rm = idx >> 3, kq = (idx & 7) << 2;
            cp_async16(As + rm * LDA_S + kq,
                       Ap + (long long)(row0 + rm) * lda + kt + kq);
        }
        float* Bs = Bbase + stage * BSZ;
        if (!TRANSB) {
            #pragma unroll
            for (int it = 0; it < NLB; it++) {
                int idx = it * THREADS + tid;
                int kk = idx / BNQ, nq = (idx % BNQ) << 2;
                cp_async16(Bs + kk * (BN + 4) + nq,
                           Bp + (long long)(kt + kk) * ldb + col0 + nq);
            }
        } else {
            #pragma unroll
            for (int it = 0; it < NLB; it++) {
                int idx = it * THREADS + tid;
                int nn = idx >> 3, kq = (idx & 7) << 2;
                cp_async16(Bs + nn * (BK + 4) + kq,
                           Bp + (long long)(col0 + nn) * ldb + kt + kq);
            }
        }
        cp_commit();
    };

    const int ntile = kEnd / BK;
    loadAB(0, 0);
    if (ntile > 1) loadAB(BK, 1);

    for (int i = 0; i < ntile; i++) {
        if (i + 1 < ntile) cp_wait<1>();
        else               cp_wait<0>();
        __syncthreads();

        if (i + 2 < ntile) loadAB((i + 2) * BK, (i + 2) % 3);

        const float* As = Abase + (i % 3) * ASZ;
        const float* Bs = Bbase + (i % 3) * BSZ;

        #pragma unroll
        for (int ks = 0; ks < 4; ks++) {
            const int kc = ks * 8 + (lane & 3);
            uint32_t aF[MT][4];
            const int ar = wm * WTM + (lane >> 2);
            #pragma unroll
            for (int mt = 0; mt < MT; mt++) {
                const float* ap = As + (ar + mt * 16) * LDA_S;
                if (CVTA) {
                    aF[mt][0] = f2tf32(ap[kc]);
                    aF[mt][1] = f2tf32(ap[8 * LDA_S + kc]);
                    aF[mt][2] = f2tf32(ap[kc + 4]);
                    aF[mt][3] = f2tf32(ap[8 * LDA_S + kc + 4]);
                } else {
                    aF[mt][0] = __float_as_uint(ap[kc]);
                    aF[mt][1] = __float_as_uint(ap[8 * LDA_S + kc]);
                    aF[mt][2] = __float_as_uint(ap[kc + 4]);
                    aF[mt][3] = __float_as_uint(ap[8 * LDA_S + kc + 4]);
                }
            }
            uint32_t bF[NT][2];
            const int c0 = wn * WTN + (lane >> 2);
            if (!TRANSB) {
                #pragma unroll
                for (int nt = 0; nt < NT; nt++) {
                    float b0 = Bs[kc * (BN + 4) + c0 + nt * 8];
                    float b1 = Bs[(kc + 4) * (BN + 4) + c0 + nt * 8];
                    bF[nt][0] = CVTB ? f2tf32(b0) : __float_as_uint(b0);
                    bF[nt][1] = CVTB ? f2tf32(b1) : __float_as_uint(b1);
                }
            } else {
                #pragma unroll
                for (int nt = 0; nt < NT; nt++) {
                    const float* bp = Bs + (c0 + nt * 8) * (BK + 4);
                    bF[nt][0] = CVTB ? f2tf32(bp[kc]) : __float_as_uint(bp[kc]);
                    bF[nt][1] = CVTB ? f2tf32(bp[kc + 4]) : __float_as_uint(bp[kc + 4]);
                }
            }
            #pragma unroll
            for (int mt = 0; mt < MT; mt++)
                #pragma unroll
                for (int nt = 0; nt < NT; nt++)
                    mma_tf32(acc[mt][nt], aF[mt], bF[nt]);
        }
    }

    #pragma unroll
    for (int mt = 0; mt < MT; mt++) {
        int rbase = row0 + wm * WTM + mt * 16 + (lane >> 2);
        #pragma unroll
        for (int nt = 0; nt < NT; nt++) {
            int c = col0 + wn * WTN + nt * 8 + (lane & 3) * 2;
            #pragma unroll
            for (int h2 = 0; h2 < 2; h2++) {
                int rr = rbase + h2 * 8;
                if (rr < M && c + 1 < N) {
                    float v0 = acc[mt][nt][h2 * 2];
                    float v1 = acc[mt][nt][h2 * 2 + 1];
                    if (EPI == 1) {
                        v0 = gelu_exact(v0 + bias[c]);
                        v1 = gelu_exact(v1 + bias[c + 1]);
                    }
                    if (EPI == 2) {
                        const float* rp = R + (long long)rr * ldr + c;
                        v0 += rp[0]; v1 += rp[1];
                    }
                    if (EPI == 3) {
                        const float* rp = R + (long long)rr * ldr + c;
                        v0 += bias[c] + rp[0]; v1 += bias[c + 1] + rp[1];
                    }
                    if (RND) { v0 = round_tf32f(v0); v1 = round_tf32f(v1); }
                    float2 o; o.x = v0; o.y = v1;
                    *(float2*)(Cp + (long long)rr * ldc + c) = o;
                }
            }
        }
    }
}

constexpr int gemm_smem(int BM, int BN, bool TRANSB) {
    return (3 * BM * 36 + 3 * (TRANSB ? BN * 36 : 32 * (BN + 4))) * 4;
}

// ---------------- ef precompute ----------------
__global__ void ef_kernel(const float* __restrict__ q, const float* __restrict__ rsb,
                          const float* __restrict__ se, float* __restrict__ ef)
{
    const int pair = blockIdx.x * 8 + (threadIdx.x >> 5);
    const int lane = threadIdx.x & 31;
    const int t = pair >> 4, n = pair & 15;
    const float* qp = q + (long long)t * 1024 + n * 64;
    float e0 = 0.f, e1 = 0.f;
    #pragma unroll
    for (int d = lane; d < 64; d += 32) {
        float qv = qp[d] + rsb[n * 64 + d];
        e0 += qv * se[n * 64 + d];
        e1 += qv * se[1024 + n * 64 + d];
    }
    #pragma unroll
    for (int o = 16; o; o >>= 1) {
        e0 += __shfl_xor_sync(0xffffffffu, e0, o);
        e1 += __shfl_xor_sync(0xffffffffu, e1, o);
    }
    if (lane == 0) {
        ef[((long long)t * 16 + n) * 2]     = e0;
        ef[((long long)t * 16 + n) * 2 + 1] = e1;
    }
}

// ---------------- paired-j fused score kernel ----------------
// One block computes TWO adjacent 64x64 score tiles (j0, j0+64) for one i-tile,
// sharing Qt and the Krt halo (191 rows). Arithmetic per element identical to
// the single-tile version. Sub-tile b is computed but not stored when j0+64 > i0.
static const int SC2_SMEM = (64 * 68 + 64 * 136 + 64 * 200 + 4 * 64 + 128) * 4;  // 104960 B

__global__ __launch_bounds__(256, 2)
void score2_kernel(const float* __restrict__ q, const float* __restrict__ k,
                   const float* __restrict__ kr,
                   const float* __restrict__ rwb, const float* __restrict__ rrb,
                   const float* __restrict__ ef, const float* __restrict__ dseg,
                   float* __restrict__ S)
{
    const int j0 = blockIdx.x * 128, i0 = blockIdx.y * 64;
    if (j0 > i0) return;                       // both sub-tiles masked
    const bool haveB = (j0 + 64 <= i0);

    const int z = blockIdx.z, b = z >> 4, n = z & 15;
    const long long sbase = (long long)z * 1048576ll;
    const int tid = threadIdx.x;

    extern __shared__ float sm[];
    float* Qt   = sm;                 // [64 d][68]
    float* Kt   = Qt + 64 * 68;       // [64 d][136] 128 j-rows
    float* Krt  = Kt + 64 * 136;      // [64 d][200] 191-row halo
    float* dbs  = Krt + 64 * 200;     // [64]
    float* efs0 = dbs + 64;
    float* efs1 = efs0 + 64;
    float* dsi  = efs1 + 64;
    float* dsj  = dsi + 64;           // [128]

    const float* qb  = q  + b * 1024 + n * 64;
    const float* kb  = k  + b * 1024 + n * 64;
    const float* krb = kr + b * 1024 + n * 64;

    for (int e = tid; e < 4096; e += 256) {
        int row = e >> 6, d = e & 63;
        Qt[d * 68 + row] = qb[(long long)(i0 + row) * 4096 + d] + rwb[n * 64 + d];
    }
    for (int e = tid; e < 8192; e += 256) {
        int row = e >> 6, d = e & 63;
        Kt[d * 136 + row] = kb[(long long)(j0 + row) * 4096 + d];
    }
    const int rel0 = j0 - i0 + 1024 - 63;
    const int nH = haveB ? 191 : 127;          // halo rows actually needed
    for (int e = tid; e < nH * 64; e += 256) {
        int row = e >> 6, d = e & 63;
        Krt[d * 200 + row] = krb[(long long)(rel0 + row) * 4096 + d];
    }
    if (tid < 64) {
        dbs[tid] = rrb[n * 64 + tid] - rwb[n * 64 + tid];
        int t = (i0 + tid) * 4 + b;
        efs0[tid] = ef[((long long)t * 16 + n) * 2];
        efs1[tid] = ef[((long long)t * 16 + n) * 2 + 1];
        dsi[tid]  = dseg[t];
    }
    if (tid < 128) dsj[tid] = dseg[(j0 + tid) * 4 + b];
    __syncthreads();

    const int tx = tid & 15, ty = tid >> 4;
    const int ib = ty * 4, jb = tx * 4;
    const int r0a = jb - ib + 60;              // [0,120]
    const int r0b = r0a + 64;                  // [64,184] (+6 -> 190 max)

    float aca[4][4] = {}, bda[4][4] = {};
    float acb[4][4] = {}, bdb[4][4] = {};
    #pragma unroll 2
    for (int kk = 0; kk < 64; kk++) {
        float db = dbs[kk];
        float qa[4], kva[4], kvb[4], kra[7], krw[7];
        #pragma unroll
        for (int a = 0; a < 4; a++) qa[a] = Qt[kk * 68 + ib + a];
        #pragma unroll
        for (int c = 0; c < 4; c++) {
            kva[c] = Kt[kk * 136 + jb + c];
            kvb[c] = Kt[kk * 136 + 64 + jb + c];
        }
        #pragma unroll
        for (int m = 0; m < 7; m++) {
            kra[m] = Krt[kk * 200 + r0a + m];
            krw[m] = Krt[kk * 200 + r0b + m];
        }
        #pragma unroll
        for (int a = 0; a < 4; a++) {
            float qd = qa[a] + db;
            #pragma unroll
            for (int c = 0; c < 4; c++) {
                aca[a][c] += qa[a] * kva[c];
                bda[a][c] += qd * kra[c - a + 3];
                acb[a][c] += qa[a] * kvb[c];
                bdb[a][c] += qd * krw[c - a + 3];
            }
        }
    }

    const bool diagA = (j0 == i0);
    const bool diagB = (j0 + 64 == i0);
    #pragma unroll
    for (int a = 0; a < 4; a++) {
        int i = i0 + ib + a;
        float e0 = efs0[ib + a], e1 = efs1[ib + a];
        float di = dsi[ib + a];
        float* srow = S + sbase + (long long)i * 1024;
        #pragma unroll
        for (int c = 0; c < 4; c++) {
            {   // sub-tile a (always stored)
                float e = (dsj[jb + c] != di) ? e1 : e0;
                float val = (aca[a][c] + bda[a][c] + e) * 0.125f;
                if (diagA && (jb + c > ib + a)) val = -1e30f;
                srow[j0 + jb + c] = val;
            }
            if (haveB) {
                float e = (dsj[64 + jb + c] != di) ? e1 : e0;
                float val = (acb[a][c] + bdb[a][c] + e) * 0.125f;
                if (diagB && (jb + c > ib + a)) val = -1e30f;
                srow[j0 + 64 + jb + c] = val;
            }
        }
    }
}

// ---------------- causal-length-aware in-place softmax (warp per row) ----------------
__global__ void softmax_kernel(float* __restrict__ S)
{
    const int row  = blockIdx.x * 8 + (threadIdx.x >> 5);
    const int lane = threadIdx.x & 31;
    const int i    = row & 1023;
    const int P64  = ((i >> 6) + 1) << 6;
    float4* p = (float4*)(S + (long long)row * 1024);
    float4 v[8];
    float mx = -3.4e38f;
    #pragma unroll
    for (int kk = 0; kk < 8; kk++) {
        int j4 = (lane + 32 * kk) * 4;
        if (j4 < P64) v[kk] = p[lane + 32 * kk];
        else          v[kk] = make_float4(-1e30f, -1e30f, -1e30f, -1e30f);
        mx = fmaxf(mx, fmaxf(fmaxf(v[kk].x, v[kk].y), fmaxf(v[kk].z, v[kk].w)));
    }
    #pragma unroll
    for (int o = 16; o; o >>= 1) mx = fmaxf(mx, __shfl_xor_sync(0xffffffffu, mx, o));
    float s = 0.f;
    #pragma unroll
    for (int kk = 0; kk < 8; kk++) {
        v[kk].x = expf(v[kk].x - mx); v[kk].y = expf(v[kk].y - mx);
        v[kk].z = expf(v[kk].z - mx); v[kk].w = expf(v[kk].w - mx);
        s += v[kk].x + v[kk].y + v[kk].z + v[kk].w;
    }
    #pragma unroll
    for (int o = 16; o; o >>= 1) s += __shfl_xor_sync(0xffffffffu, s, o);
    float inv = 1.0f / s;
    #pragma unroll
    for (int kk = 0; kk < 8; kk++) {
        int j4 = (lane + 32 * kk) * 4;
        if (j4 < P64) {
            v[kk].x = round_tf32f(v[kk].x * inv);
            v[kk].y = round_tf32f(v[kk].y * inv);
            v[kk].z = round_tf32f(v[kk].z * inv);
            v[kk].w = round_tf32f(v[kk].w * inv);
            p[lane + 32 * kk] = v[kk];
        }
    }
}

// ---------------- layernorm ----------------
__global__ void ln_kernel(const float* __restrict__ X, const float* __restrict__ gw,
                          const float* __restrict__ bw, float* __restrict__ Y)
{
    __shared__ float red[8];
    __shared__ float stat[2];
    const int row = blockIdx.x;
    const int tid = threadIdx.x;
    const int lane = tid & 31, wid = tid >> 5;
    float4 x = ((const float4*)(X + (long long)row * 1024))[tid];

    float s = x.x + x.y + x.z + x.w;
    #pragma unroll
    for (int o = 16; o; o >>= 1) s += __shfl_xor_sync(0xffffffffu, s, o);
    if (lane == 0) red[wid] = s;
    __syncthreads();
    if (tid == 0) {
        float t = 0.f;
        for (int i = 0; i < 8; i++) t += red[i];
        stat[0] = t * (1.0f / 1024.0f);
    }
    __syncthreads();
    float mu = stat[0];
    float d0 = x.x - mu, d1 = x.y - mu, d2 = x.z - mu, d3 = x.w - mu;
    float sq = d0 * d0 + d1 * d1 + d2 * d2 + d3 * d3;
    #pragma unroll
    for (int o = 16; o; o >>= 1) sq += __shfl_xor_sync(0xffffffffu, sq, o);
    if (lane == 0) red[wid] = sq;
    __syncthreads();
    if (tid == 0) {
        float t = 0.f;
        for (int i = 0; i < 8; i++) t += red[i];
        stat[1] = rsqrtf(t * (1.0f / 1024.0f) + 1e-12f);
    }
    __syncthreads();
    float rs = stat[1];
    float4 g4 = ((const float4*)gw)[tid];
    float4 b4 = ((const float4*)bw)[tid];
    float4 y;
    y.x = d0 * rs * g4.x + b4.x;
    y.y = d1 * rs * g4.y + b4.y;
    y.z = d2 * rs * g4.z + b4.z;
    y.w = d3 * rs * g4.w + b4.w;
    ((float4*)(Y + (long long)row * 1024))[tid] = y;
}

// ---------------- orchestration ----------------
extern "C" void kernel_launch(void* const* d_in, const int* in_sizes, int n_in,
                              void* d_out, int out_size)
{
    (void)in_sizes; (void)n_in; (void)out_size;
    const float* h    = (const float*)d_in[0];
    const float* r    = (const float*)d_in[1];
    const float* segm = (const float*)d_in[3];
    const float* q_w  = (const float*)d_in[4];
    const float* k_w  = (const float*)d_in[5];
    const float* v_w  = (const float*)d_in[6];
    const float* o_w  = (const float*)d_in[7];
    const float* r_w  = (const float*)d_in[8];
    const float* rrb  = (const float*)d_in[9];
    const float* rsb  = (const float*)d_in[10];
    const float* rwb  = (const float*)d_in[11];
    const float* se   = (const float*)d_in[12];
    const float* ln1g = (const float*)d_in[13];
    const float* ln1b = (const float*)d_in[14];
    const float* w1   = (const float*)d_in[15];
    const float* b1   = (const float*)d_in[16];
    const float* w2   = (const float*)d_in[17];
    const float* b2   = (const float*)d_in[18];
    const float* ln2g = (const float*)d_in[19];
    const float* ln2b = (const float*)d_in[20];
    float* out = (float*)d_out;

    float *gqkv, *gkr, *gef, *gsg, *gs, *gav, *gpre, *go1, *gffh, *gp2;
    float *ght, *gwqkv, *gwo, *gwr, *gw1t, *gw2t;
    cudaGetSymbolAddress((void**)&gqkv, g_qkv);
    cudaGetSymbolAddress((void**)&gkr,  g_kr);
    cudaGetSymbolAddress((void**)&gef,  g_ef);
    cudaGetSymbolAddress((void**)&gsg,  g_sg);
    cudaGetSymbolAddress((void**)&gs,   g_s);
    cudaGetSymbolAddress((void**)&gav,  g_av);
    cudaGetSymbolAddress((void**)&gpre, g_pre);
    cudaGetSymbolAddress((void**)&go1,  g_o1);
    cudaGetSymbolAddress((void**)&gffh, g_ffh);
    cudaGetSymbolAddress((void**)&gp2,  g_p2);
    cudaGetSymbolAddress((void**)&ght,  g_ht);
    cudaGetSymbolAddress((void**)&gwqkv, g_wqkv);
    cudaGetSymbolAddress((void**)&gwo,  g_wo);
    cudaGetSymbolAddress((void**)&gwr,  g_wr);
    cudaGetSymbolAddress((void**)&gw1t, g_w1t);
    cudaGetSymbolAddress((void**)&gw2t, g_w2t);

    float* gq = gqkv;
    float* gk = gqkv + 4194304;
    float* gv = gqkv + 8388608;

    const int SM_NRM = gemm_smem(128, 128, false);
    const int SM_TRB = gemm_smem(128, 128, true);
    const int SM_PV  = gemm_smem(64, 64, false);

    cudaFuncSetAttribute(score2_kernel, cudaFuncAttributeMaxDynamicSharedMemorySize, SC2_SMEM);
    cudaFuncSetAttribute((const void*)gemm_tc<128,128,4,2,false,0,false,false,false>,
                         cudaFuncAttributeMaxDynamicSharedMemorySize, SM_NRM);
    cudaFuncSetAttribute((const void*)gemm_tc<128,128,4,2,true,2,false,false,false>,
                         cudaFuncAttributeMaxDynamicSharedMemorySize, SM_TRB);
    cudaFuncSetAttribute((const void*)gemm_tc<128,128,4,2,false,1,true,false,true>,
                         cudaFuncAttributeMaxDynamicSharedMemorySize, SM_NRM);
    cudaFuncSetAttribute((const void*)gemm_tc<128,128,4,2,false,3,false,false,false>,
                         cudaFuncAttributeMaxDynamicSharedMemorySize, SM_NRM);
    cudaFuncSetAttribute((const void*)gemm_tc<64,64,4,2,false,0,false,true,true>,
                         cudaFuncAttributeMaxDynamicSharedMemorySize, SM_PV);

    // pre-round pure GEMM operands to tf32
    round_kernel<<<4096,256>>>((const float4*)h,   (float4*)ght,  4194304/4);
    round3_kernel<<<3072,256>>>((const float4*)q_w, (const float4*)k_w, (const float4*)v_w,
                                (float4*)gwqkv, 1048576/4);
    round_kernel<<<1024,256>>>((const float4*)o_w, (float4*)gwo,  1048576/4);
    round_kernel<<<1024,256>>>((const float4*)r_w, (float4*)gwr,  1048576/4);
    round_kernel<<<4096,256>>>((const float4*)w1,  (float4*)gw1t, 4194304/4);
    round_kernel<<<4096,256>>>((const float4*)w2,  (float4*)gw2t, 4194304/4);
    seg_kernel<<<16,256>>>(segm, gsg);

    // q/k/v projections: one batched launch
    gemm_tc<128,128,4,2,false,0,false,false,false><<<dim3(8,32,3),256,SM_NRM>>>(ght, gwqkv, gqkv,
        nullptr, nullptr, NTOK, DMODEL, DMODEL, 1024,1024,1024,0,
        0, 0, 0, 1048576ll, 0, 4194304ll, 0);
    // relative projection: only rel rows <= 1087 are read
    gemm_tc<128,128,4,2,false,0,false,false,false><<<dim3(8,34,1),256,SM_NRM>>>(r, gwr, gkr,
        nullptr, nullptr, RTOK, DMODEL, DMODEL, 1024,1024,1024,0, 0,0,0,0,0,0, 0);

    ef_kernel<<<8192,256>>>(gq, rsb, se, gef);
    score2_kernel<<<dim3(8,16,64),256,SC2_SMEM>>>(gq, gk, gkr, rwb, rrb, gef, gsg, gs);
    softmax_kernel<<<8192,256>>>(gs);

    // attn_vec = P @ V (batched, causal K-truncation); v rounded at B-fragment load
    gemm_tc<64,64,4,2,false,0,false,true,true><<<dim3(1,16,64),256,SM_PV>>>(gs, gv, gav,
        nullptr, nullptr, 1024, 64, 1024, 1024,4096,4096,0,
        16ll*1048576ll, 1048576ll, 1024ll, 64ll, 1024ll, 64ll, 1);

    // o-projection (B transposed, pre-rounded) + residual h (fp32)
    gemm_tc<128,128,4,2,true,2,false,false,false><<<dim3(8,32,1),256,SM_TRB>>>(gav, gwo, gpre,
        nullptr, h, NTOK, DMODEL, DMODEL, 1024,1024,1024,1024, 0,0,0,0,0,0, 0);
    ln_kernel<<<4096,256>>>(gpre, ln1g, ln1b, go1);

    // FF1 (+bias, GELU) and FF2 (+bias, +residual)
    gemm_tc<128,128,4,2,false,1,true,false,true><<<dim3(32,32,1),256,SM_NRM>>>(go1, gw1t, gffh,
        b1, nullptr, NTOK, DFF, DMODEL, 1024,4096,4096,0, 0,0,0,0,0,0, 0);
    gemm_tc<128,128,4,2,false,3,false,false,false><<<dim3(8,32,1),256,SM_NRM>>>(gffh, gw2t, gp2,
        b2, go1, NTOK, DMODEL, DFF, 4096,1024,1024,1024, 0,0,0,0,0,0, 0);
    ln_kernel<<<4096,256>>>(gp2, ln2g, ln2b, out);
}

// round 13
// speedup vs baseline: 1.0683x; 1.0528x over previous
#include <cuda_runtime.h>
#include <math.h>
#include <stdint.h>

// ---------------- problem constants ----------------
#define NTOK   4096      // QLEN*B
#define RTOK   8192      // RLEN*B
#define DMODEL 1024
#define NHEAD  16
#define DHEAD  64
#define DFF    4096

// ---------------- scratch (__device__ globals; allocation-free) ----------------
__device__ float g_qkv [3 * 4096 * 1024];  // contiguous q|k|v
__device__ float g_kr  [8192 * 1024];
__device__ float g_ef  [4096 * 16 * 2];
__device__ float g_sg  [4096];             // d[i*4+b] = (seg_i != seg_0)
__device__ float g_s   [67108864];         // scores->probs in place
__device__ float g_av  [4096 * 1024];
__device__ float g_pre [4096 * 1024];
__device__ float g_o1  [4096 * 1024];
__device__ float g_ffh [4096 * 4096];
__device__ float g_p2  [4096 * 1024];
// tf32-pre-rounded operands (numerically identical to per-load cvt)
__device__ float g_ht  [4096 * 1024];
__device__ float g_wqkv[3 * 1024 * 1024];  // contiguous q_w|k_w|v_w rounded
__device__ float g_wo  [1024 * 1024];
__device__ float g_wr  [1024 * 1024];
__device__ float g_w1t [1024 * 4096];
__device__ float g_w2t [4096 * 1024];

__device__ __forceinline__ float gelu_exact(float x) {
    return 0.5f * x * (1.0f + erff(x * 0.70710678118654752f));
}
__device__ __forceinline__ uint32_t f2tf32(float x) {
    uint32_t u; asm("cvt.rna.tf32.f32 %0, %1;" : "=r"(u) : "f"(x)); return u;
}
__device__ __forceinline__ float round_tf32f(float x) { return __uint_as_float(f2tf32(x)); }

__device__ __forceinline__ void mma_tf32(float* c, const uint32_t* a, const uint32_t* b) {
    asm volatile(
        "mma.sync.aligned.m16n8k8.row.col.f32.tf32.tf32.f32 "
        "{%0,%1,%2,%3}, {%4,%5,%6,%7}, {%8,%9}, {%0,%1,%2,%3};\n"
        : "+f"(c[0]), "+f"(c[1]), "+f"(c[2]), "+f"(c[3])
        : "r"(a[0]), "r"(a[1]), "r"(a[2]), "r"(a[3]), "r"(b[0]), "r"(b[1]));
}
__device__ __forceinline__ void cp_async16(float* s, const float* g) {
    uint32_t sa = (uint32_t)__cvta_generic_to_shared(s);
    asm volatile("cp.async.cg.shared.global [%0], [%1], 16;" :: "r"(sa), "l"(g));
}
__device__ __forceinline__ void cp_commit() { asm volatile("cp.async.commit_group;"); }
template<int N> __device__ __forceinline__ void cp_wait() {
    asm volatile("cp.async.wait_group %0;" :: "n"(N));
}

// ---------------- elementwise tf32 rounding passes ----------------
// h-round + fused seg extraction in the last 16 blocks' spare capacity
__global__ void round_h_seg_kernel(const float4* __restrict__ src, float4* __restrict__ dst,
                                   int n4, const float* __restrict__ segm,
                                   float* __restrict__ dseg)
{
    int i = blockIdx.x * 256 + threadIdx.x;
    if (i < n4) {
        float4 v = src[i];
        v.x = round_tf32f(v.x); v.y = round_tf32f(v.y);
        v.z = round_tf32f(v.z); v.w = round_tf32f(v.w);
        dst[i] = v;
    }
    int t = i - (n4 - 4096);               // last 4096 lanes also extract seg
    if (t >= 0 && t < 4096) {
        int r_ = t >> 2, b = t & 3;
        dseg[t] = segm[(long long)r_ * 8192 + b * 2 + 1];
    }
}
__global__ void round_kernel(const float4* __restrict__ src, float4* __restrict__ dst, int n4)
{
    int i = blockIdx.x * 256 + threadIdx.x;
    if (i < n4) {
        float4 v = src[i];
        v.x = round_tf32f(v.x); v.y = round_tf32f(v.y);
        v.z = round_tf32f(v.z); v.w = round_tf32f(v.w);
        dst[i] = v;
    }
}
// two equal-size tensors in one launch
__global__ void round2_kernel(const float4* __restrict__ s0, float4* __restrict__ d0,
                              const float4* __restrict__ s1, float4* __restrict__ d1,
                              int n4per)
{
    int i = blockIdx.x * 256 + threadIdx.x;
    if (i < 2 * n4per) {
        const float4* s = (i < n4per) ? s0 : s1;
        float4*       d = (i < n4per) ? d0 : d1;
        int idx = (i < n4per) ? i : i - n4per;
        float4 v = s[idx];
        v.x = round_tf32f(v.x); v.y = round_tf32f(v.y);
        v.z = round_tf32f(v.z); v.w = round_tf32f(v.w);
        d[idx] = v;
    }
}
// three equal-size tensors -> one contiguous rounded buffer
__global__ void round3_kernel(const float4* __restrict__ s0, const float4* __restrict__ s1,
                              const float4* __restrict__ s2, float4* __restrict__ dst, int n4per)
{
    int i = blockIdx.x * 256 + threadIdx.x;
    if (i < 3 * n4per) {
        const float4* s = (i < n4per) ? s0 : (i < 2 * n4per ? s1 : s2);
        int idx = i - (i < n4per ? 0 : (i < 2 * n4per ? n4per : 2 * n4per));
        float4 v = s[idx];
        v.x = round_tf32f(v.x); v.y = round_tf32f(v.y);
        v.z = round_tf32f(v.z); v.w = round_tf32f(v.w);
        dst[i] = v;
    }
}

// ---------------- tf32 tensor-core GEMM, 3-stage cp.async ----------------
template<int BM, int BN, int WGM, int WGN, bool TRANSB, int EPI, bool CVTA, bool CVTB, bool RND>
__global__ __launch_bounds__(WGM * WGN * 32, 2)
void gemm_tc(const float* __restrict__ A, const float* __restrict__ B,
             float* __restrict__ C, const float* __restrict__ bias,
             const float* __restrict__ R,
             int M, int N, int K, int lda, int ldb, int ldc, int ldr,
             long long sAb, long long sAn, long long sBb, long long sBn,
             long long sCb, long long sCn, int causal)
{
    constexpr int BK = 32;
    constexpr int THREADS = WGM * WGN * 32;
    constexpr int WTM = BM / WGM, WTN = BN / WGN;
    constexpr int MT = WTM / 16, NT = WTN / 8;
    constexpr int LDA_S = BK + 4;
    constexpr int ASZ = BM * LDA_S;
    constexpr int BSZ = TRANSB ? BN * (BK + 4) : BK * (BN + 4);
    constexpr int NLA = BM * BK / (4 * THREADS);
    constexpr int NLB = BN * BK / (4 * THREADS);
    constexpr int BNQ = BN / 4;

    extern __shared__ float sm[];
    float* Abase = sm;
    float* Bbase = sm + 3 * ASZ;

    const int tid  = threadIdx.x;
    const int lane = tid & 31;
    const int warp = tid >> 5;
    const int wm = warp / WGN, wn = warp % WGN;

    const int zb = blockIdx.z >> 4, zn = blockIdx.z & 15;
    const float* Ap = A + zb * sAb + zn * sAn;
    const float* Bp = B + zb * sBb + zn * sBn;
    float*       Cp = C + zb * sCb + zn * sCn;

    const int row0 = blockIdx.y * BM;
    const int col0 = blockIdx.x * BN;
    const int kEnd = causal ? ((row0 + BM < K) ? (row0 + BM) : K) : K;

    float acc[MT][NT][4];
    #pragma unroll
    for (int mt = 0; mt < MT; mt++)
        #pragma unroll
        for (int nt = 0; nt < NT; nt++)
            #pragma unroll
            for (int q = 0; q < 4; q++) acc[mt][nt][q] = 0.0f;

    auto loadAB = [&](int kt, int stage) {
        float* As = Abase + stage * ASZ;
        #pragma unroll
        for (int it = 0; it < NLA; it++) {
            int idx = it * THREADS + tid;
            int rm = idx >> 3, kq = (idx & 7) << 2;
            cp_async16(As + rm * LDA_S + kq,
                       Ap + (long long)(row0 + rm) * lda + kt + kq);
        }
        float* Bs = Bbase + stage * BSZ;
        if (!TRANSB) {
            #pragma unroll
            for (int it = 0; it < NLB; it++) {
                int idx = it * THREADS + tid;
                int kk = idx / BNQ, nq = (idx % BNQ) << 2;
                cp_async16(Bs + kk * (BN + 4) + nq,
                           Bp + (long long)(kt + kk) * ldb + col0 + nq);
            }
        } else {
            #pragma unroll
            for (int it = 0; it < NLB; it++) {
                int idx = it * THREADS + tid;
                int nn = idx >> 3, kq = (idx & 7) << 2;
                cp_async16(Bs + nn * (BK + 4) + kq,
                           Bp + (long long)(col0 + nn) * ldb + kt + kq);
            }
        }
        cp_commit();
    };

    const int ntile = kEnd / BK;
    loadAB(0, 0);
    if (ntile > 1) loadAB(BK, 1);

    for (int i = 0; i < ntile; i++) {
        if (i + 1 < ntile) cp_wait<1>();
        else               cp_wait<0>();
        __syncthreads();

        if (i + 2 < ntile) loadAB((i + 2) * BK, (i + 2) % 3);

        const float* As = Abase + (i % 3) * ASZ;
        const float* Bs = Bbase + (i % 3) * BSZ;

        #pragma unroll
        for (int ks = 0; ks < 4; ks++) {
            const int kc = ks * 8 + (lane & 3);
            uint32_t aF[MT][4];
            const int ar = wm * WTM + (lane >> 2);
            #pragma unroll
            for (int mt = 0; mt < MT; mt++) {
                const float* ap = As + (ar + mt * 16) * LDA_S;
                if (CVTA) {
                    aF[mt][0] = f2tf32(ap[kc]);
                    aF[mt][1] = f2tf32(ap[8 * LDA_S + kc]);
                    aF[mt][2] = f2tf32(ap[kc + 4]);
                    aF[mt][3] = f2tf32(ap[8 * LDA_S + kc + 4]);
                } else {
                    aF[mt][0] = __float_as_uint(ap[kc]);
                    aF[mt][1] = __float_as_uint(ap[8 * LDA_S + kc]);
                    aF[mt][2] = __float_as_uint(ap[kc + 4]);
                    aF[mt][3] = __float_as_uint(ap[8 * LDA_S + kc + 4]);
                }
            }
            uint32_t bF[NT][2];
            const int c0 = wn * WTN + (lane >> 2);
            if (!TRANSB) {
                #pragma unroll
                for (int nt = 0; nt < NT; nt++) {
                    float b0 = Bs[kc * (BN + 4) + c0 + nt * 8];
                    float b1 = Bs[(kc + 4) * (BN + 4) + c0 + nt * 8];
                    bF[nt][0] = CVTB ? f2tf32(b0) : __float_as_uint(b0);
                    bF[nt][1] = CVTB ? f2tf32(b1) : __float_as_uint(b1);
                }
            } else {
                #pragma unroll
                for (int nt = 0; nt < NT; nt++) {
                    const float* bp = Bs + (c0 + nt * 8) * (BK + 4);
                    bF[nt][0] = CVTB ? f2tf32(bp[kc]) : __float_as_uint(bp[kc]);
                    bF[nt][1] = CVTB ? f2tf32(bp[kc + 4]) : __float_as_uint(bp[kc + 4]);
                }
            }
            #pragma unroll
            for (int mt = 0; mt < MT; mt++)
                #pragma unroll
                for (int nt = 0; nt < NT; nt++)
                    mma_tf32(acc[mt][nt], aF[mt], bF[nt]);
        }
    }

    #pragma unroll
    for (int mt = 0; mt < MT; mt++) {
        int rbase = row0 + wm * WTM + mt * 16 + (lane >> 2);
        #pragma unroll
        for (int nt = 0; nt < NT; nt++) {
            int c = col0 + wn * WTN + nt * 8 + (lane & 3) * 2;
            #pragma unroll
            for (int h2 = 0; h2 < 2; h2++) {
                int rr = rbase + h2 * 8;
                if (rr < M && c + 1 < N) {
                    float v0 = acc[mt][nt][h2 * 2];
                    float v1 = acc[mt][nt][h2 * 2 + 1];
                    if (EPI == 1) {
                        v0 = gelu_exact(v0 + bias[c]);
                        v1 = gelu_exact(v1 + bias[c + 1]);
                    }
                    if (EPI == 2) {
                        const float* rp = R + (long long)rr * ldr + c;
                        v0 += rp[0]; v1 += rp[1];
                    }
                    if (EPI == 3) {
                        const float* rp = R + (long long)rr * ldr + c;
                        v0 += bias[c] + rp[0]; v1 += bias[c + 1] + rp[1];
                    }
                    if (RND) { v0 = round_tf32f(v0); v1 = round_tf32f(v1); }
                    float2 o; o.x = v0; o.y = v1;
                    *(float2*)(Cp + (long long)rr * ldc + c) = o;
                }
            }
        }
    }
}

constexpr int gemm_smem(int BM, int BN, bool TRANSB) {
    return (3 * BM * 36 + 3 * (TRANSB ? BN * 36 : 32 * (BN + 4))) * 4;
}

// ---------------- ef precompute ----------------
__global__ void ef_kernel(const float* __restrict__ q, const float* __restrict__ rsb,
                          const float* __restrict__ se, float* __restrict__ ef)
{
    const int pair = blockIdx.x * 8 + (threadIdx.x >> 5);
    const int lane = threadIdx.x & 31;
    const int t = pair >> 4, n = pair & 15;
    const float* qp = q + (long long)t * 1024 + n * 64;
    float e0 = 0.f, e1 = 0.f;
    #pragma unroll
    for (int d = lane; d < 64; d += 32) {
        float qv = qp[d] + rsb[n * 64 + d];
        e0 += qv * se[n * 64 + d];
        e1 += qv * se[1024 + n * 64 + d];
    }
    #pragma unroll
    for (int o = 16; o; o >>= 1) {
        e0 += __shfl_xor_sync(0xffffffffu, e0, o);
        e1 += __shfl_xor_sync(0xffffffffu, e1, o);
    }
    if (lane == 0) {
        ef[((long long)t * 16 + n) * 2]     = e0;
        ef[((long long)t * 16 + n) * 2 + 1] = e1;
    }
}

// ---------------- fused score kernel (R9-verified single-tile form) ----------------
static const int SCORE_SMEM = (64 * 68 * 2 + 64 * 132 + 64 * 5) * 4;

__global__ __launch_bounds__(256)
void score_kernel(const float* __restrict__ q, const float* __restrict__ k,
                  const float* __restrict__ kr,
                  const float* __restrict__ rwb, const float* __restrict__ rrb,
                  const float* __restrict__ ef, const float* __restrict__ dseg,
                  float* __restrict__ S)
{
    const int j0 = blockIdx.x * 64, i0 = blockIdx.y * 64;
    if (j0 > i0) return;

    const int z = blockIdx.z, b = z >> 4, n = z & 15;
    const long long sbase = (long long)z * 1048576ll;
    const int tid = threadIdx.x;

    extern __shared__ float sm[];
    float* Qt   = sm;
    float* Kt   = Qt + 64 * 68;
    float* Krt  = Kt + 64 * 68;
    float* dbs  = Krt + 64 * 132;
    float* efs0 = dbs + 64;
    float* efs1 = efs0 + 64;
    float* dsi  = efs1 + 64;
    float* dsj  = dsi + 64;

    const float* qb  = q  + b * 1024 + n * 64;
    const float* kb  = k  + b * 1024 + n * 64;
    const float* krb = kr + b * 1024 + n * 64;

    for (int e = tid; e < 4096; e += 256) {
        int row = e >> 6, d = e & 63;
        Qt[d * 68 + row] = qb[(long long)(i0 + row) * 4096 + d] + rwb[n * 64 + d];
        Kt[d * 68 + row] = kb[(long long)(j0 + row) * 4096 + d];
    }
    const int rel0 = j0 - i0 + 1024 - 63;
    for (int e = tid; e < 127 * 64; e += 256) {
        int row = e >> 6, d = e & 63;
        Krt[d * 132 + row] = krb[(long long)(rel0 + row) * 4096 + d];
    }
    if (tid < 64) {
        dbs[tid] = rrb[n * 64 + tid] - rwb[n * 64 + tid];
        int t = (i0 + tid) * 4 + b;
        efs0[tid] = ef[((long long)t * 16 + n) * 2];
        efs1[tid] = ef[((long long)t * 16 + n) * 2 + 1];
        dsi[tid]  = dseg[t];
        dsj[tid]  = dseg[(j0 + tid) * 4 + b];
    }
    __syncthreads();

    const int tx = tid & 15, ty = tid >> 4;
    const int ib = ty * 4, jb = tx * 4;
    const int r0 = jb - ib + 60;

    float ac[4][4] = {}, bd[4][4] = {};
    #pragma unroll 4
    for (int kk = 0; kk < 64; kk++) {
        float db = dbs[kk];
        float qa[4], kv[4], krv[7];
        #pragma unroll
        for (int a = 0; a < 4; a++) qa[a] = Qt[kk * 68 + ib + a];
        #pragma unroll
        for (int c = 0; c < 4; c++) kv[c] = Kt[kk * 68 + jb + c];
        #pragma unroll
        for (int m = 0; m < 7; m++) krv[m] = Krt[kk * 132 + r0 + m];
        #pragma unroll
        for (int a = 0; a < 4; a++) {
            float qd = qa[a] + db;
            #pragma unroll
            for (int c = 0; c < 4; c++) {
                ac[a][c] += qa[a] * kv[c];
                bd[a][c] += qd * krv[c - a + 3];
            }
        }
    }

    const bool diag = (i0 == j0);
    #pragma unroll
    for (int a = 0; a < 4; a++) {
        int i = i0 + ib + a;
        float e0 = efs0[ib + a], e1 = efs1[ib + a];
        float di = dsi[ib + a];
        #pragma unroll
        for (int c = 0; c < 4; c++) {
            int j = j0 + jb + c;
            float e = (dsj[jb + c] != di) ? e1 : e0;
            float val = (ac[a][c] + bd[a][c] + e) * 0.125f;
            if (diag && (jb + c > ib + a)) val = -1e30f;
            S[sbase + (long long)i * 1024 + j] = val;
        }
    }
}

// ---------------- causal-length-aware in-place softmax (warp per row) ----------------
__global__ void softmax_kernel(float* __restrict__ S)
{
    const int row  = blockIdx.x * 8 + (threadIdx.x >> 5);
    const int lane = threadIdx.x & 31;
    const int i    = row & 1023;
    const int P64  = ((i >> 6) + 1) << 6;
    float4* p = (float4*)(S + (long long)row * 1024);
    float4 v[8];
    float mx = -3.4e38f;
    #pragma unroll
    for (int kk = 0; kk < 8; kk++) {
        int j4 = (lane + 32 * kk) * 4;
        if (j4 < P64) v[kk] = p[lane + 32 * kk];
        else          v[kk] = make_float4(-1e30f, -1e30f, -1e30f, -1e30f);
        mx = fmaxf(mx, fmaxf(fmaxf(v[kk].x, v[kk].y), fmaxf(v[kk].z, v[kk].w)));
    }
    #pragma unroll
    for (int o = 16; o; o >>= 1) mx = fmaxf(mx, __shfl_xor_sync(0xffffffffu, mx, o));
    float s = 0.f;
    #pragma unroll
    for (int kk = 0; kk < 8; kk++) {
        v[kk].x = expf(v[kk].x - mx); v[kk].y = expf(v[kk].y - mx);
        v[kk].z = expf(v[kk].z - mx); v[kk].w = expf(v[kk].w - mx);
        s += v[kk].x + v[kk].y + v[kk].z + v[kk].w;
    }
    #pragma unroll
    for (int o = 16; o; o >>= 1) s += __shfl_xor_sync(0xffffffffu, s, o);
    float inv = 1.0f / s;
    #pragma unroll
    for (int kk = 0; kk < 8; kk++) {
        int j4 = (lane + 32 * kk) * 4;
        if (j4 < P64) {
            v[kk].x = round_tf32f(v[kk].x * inv);
            v[kk].y = round_tf32f(v[kk].y * inv);
            v[kk].z = round_tf32f(v[kk].z * inv);
            v[kk].w = round_tf32f(v[kk].w * inv);
            p[lane + 32 * kk] = v[kk];
        }
    }
}

// ---------------- layernorm ----------------
__global__ void ln_kernel(const float* __restrict__ X, const float* __restrict__ gw,
                          const float* __restrict__ bw, float* __restrict__ Y)
{
    __shared__ float red[8];
    __shared__ float stat[2];
    const int row = blockIdx.x;
    const int tid = threadIdx.x;
    const int lane = tid & 31, wid = tid >> 5;
    float4 x = ((const float4*)(X + (long long)row * 1024))[tid];

    float s = x.x + x.y + x.z + x.w;
    #pragma unroll
    for (int o = 16; o; o >>= 1) s += __shfl_xor_sync(0xffffffffu, s, o);
    if (lane == 0) red[wid] = s;
    __syncthreads();
    if (tid == 0) {
        float t = 0.f;
        for (int i = 0; i < 8; i++) t += red[i];
        stat[0] = t * (1.0f / 1024.0f);
    }
    __syncthreads();
    float mu = stat[0];
    float d0 = x.x - mu, d1 = x.y - mu, d2 = x.z - mu, d3 = x.w - mu;
    float sq = d0 * d0 + d1 * d1 + d2 * d2 + d3 * d3;
    #pragma unroll
    for (int o = 16; o; o >>= 1) sq += __shfl_xor_sync(0xffffffffu, sq, o);
    if (lane == 0) red[wid] = sq;
    __syncthreads();
    if (tid == 0) {
        float t = 0.f;
        for (int i = 0; i < 8; i++) t += red[i];
        stat[1] = rsqrtf(t * (1.0f / 1024.0f) + 1e-12f);
    }
    __syncthreads();
    float rs = stat[1];
    float4 g4 = ((const float4*)gw)[tid];
    float4 b4 = ((const float4*)bw)[tid];
    float4 y;
    y.x = d0 * rs * g4.x + b4.x;
    y.y = d1 * rs * g4.y + b4.y;
    y.z = d2 * rs * g4.z + b4.z;
    y.w = d3 * rs * g4.w + b4.w;
    ((float4*)(Y + (long long)row * 1024))[tid] = y;
}

// ---------------- orchestration ----------------
extern "C" void kernel_launch(void* const* d_in, const int* in_sizes, int n_in,
                              void* d_out, int out_size)
{
    (void)in_sizes; (void)n_in; (void)out_size;
    const float* h    = (const float*)d_in[0];
    const float* r    = (const float*)d_in[1];
    const float* segm = (const float*)d_in[3];
    const float* q_w  = (const float*)d_in[4];
    const float* k_w  = (const float*)d_in[5];
    const float* v_w  = (const float*)d_in[6];
    const float* o_w  = (const float*)d_in[7];
    const float* r_w  = (const float*)d_in[8];
    const float* rrb  = (const float*)d_in[9];
    const float* rsb  = (const float*)d_in[10];
    const float* rwb  = (const float*)d_in[11];
    const float* se   = (const float*)d_in[12];
    const float* ln1g = (const float*)d_in[13];
    const float* ln1b = (const float*)d_in[14];
    const float* w1   = (const float*)d_in[15];
    const float* b1   = (const float*)d_in[16];
    const float* w2   = (const float*)d_in[17];
    const float* b2   = (const float*)d_in[18];
    const float* ln2g = (const float*)d_in[19];
    const float* ln2b = (const float*)d_in[20];
    float* out = (float*)d_out;

    float *gqkv, *gkr, *gef, *gsg, *gs, *gav, *gpre, *go1, *gffh, *gp2;
    float *ght, *gwqkv, *gwo, *gwr, *gw1t, *gw2t;
    cudaGetSymbolAddress((void**)&gqkv, g_qkv);
    cudaGetSymbolAddress((void**)&gkr,  g_kr);
    cudaGetSymbolAddress((void**)&gef,  g_ef);
    cudaGetSymbolAddress((void**)&gsg,  g_sg);
    cudaGetSymbolAddress((void**)&gs,   g_s);
    cudaGetSymbolAddress((void**)&gav,  g_av);
    cudaGetSymbolAddress((void**)&gpre, g_pre);
    cudaGetSymbolAddress((void**)&go1,  g_o1);
    cudaGetSymbolAddress((void**)&gffh, g_ffh);
    cudaGetSymbolAddress((void**)&gp2,  g_p2);
    cudaGetSymbolAddress((void**)&ght,  g_ht);
    cudaGetSymbolAddress((void**)&gwqkv, g_wqkv);
    cudaGetSymbolAddress((void**)&gwo,  g_wo);
    cudaGetSymbolAddress((void**)&gwr,  g_wr);
    cudaGetSymbolAddress((void**)&gw1t, g_w1t);
    cudaGetSymbolAddress((void**)&gw2t, g_w2t);

    float* gq = gqkv;
    float* gk = gqkv + 4194304;
    float* gv = gqkv + 8388608;

    const int SM_NRM = gemm_smem(128, 128, false);
    const int SM_TRB = gemm_smem(128, 128, true);
    const int SM_PV  = gemm_smem(64, 64, false);

    cudaFuncSetAttribute(score_kernel, cudaFuncAttributeMaxDynamicSharedMemorySize, SCORE_SMEM);
    cudaFuncSetAttribute((const void*)gemm_tc<128,128,4,2,false,0,false,false,false>,
                         cudaFuncAttributeMaxDynamicSharedMemorySize, SM_NRM);
    cudaFuncSetAttribute((const void*)gemm_tc<128,128,4,2,true,2,false,false,false>,
                         cudaFuncAttributeMaxDynamicSharedMemorySize, SM_TRB);
    cudaFuncSetAttribute((const void*)gemm_tc<128,128,4,2,false,1,true,false,true>,
                         cudaFuncAttributeMaxDynamicSharedMemorySize, SM_NRM);
    cudaFuncSetAttribute((const void*)gemm_tc<128,128,4,2,false,3,false,false,false>,
                         cudaFuncAttributeMaxDynamicSharedMemorySize, SM_NRM);
    cudaFuncSetAttribute((const void*)gemm_tc<64,64,4,2,false,0,false,true,true>,
                         cudaFuncAttributeMaxDynamicSharedMemorySize, SM_PV);

    // pre-round pure GEMM operands to tf32 (numerically identical to per-load cvt)
    round_h_seg_kernel<<<4096,256>>>((const float4*)h, (float4*)ght, 4194304/4, segm, gsg);
    round3_kernel<<<3072,256>>>((const float4*)q_w, (const float4*)k_w, (const float4*)v_w,
                                (float4*)gwqkv, 1048576/4);
    round2_kernel<<<2048,256>>>((const float4*)o_w, (float4*)gwo,
                                (const float4*)r_w, (float4*)gwr, 1048576/4);
    round2_kernel<<<8192,256>>>((const float4*)w1,  (float4*)gw1t,
                                (const float4*)w2,  (float4*)gw2t, 4194304/4);

    // q/k/v projections: one batched launch
    gemm_tc<128,128,4,2,false,0,false,false,false><<<dim3(8,32,3),256,SM_NRM>>>(ght, gwqkv, gqkv,
        nullptr, nullptr, NTOK, DMODEL, DMODEL, 1024,1024,1024,0,
        0, 0, 0, 1048576ll, 0, 4194304ll, 0);
    // relative projection: only rel rows <= 1087 are read
    gemm_tc<128,128,4,2,false,0,false,false,false><<<dim3(8,34,1),256,SM_NRM>>>(r, gwr, gkr,
        nullptr, nullptr, RTOK, DMODEL, DMODEL, 1024,1024,1024,0, 0,0,0,0,0,0, 0);

    ef_kernel<<<8192,256>>>(gq, rsb, se, gef);
    score_kernel<<<dim3(16,16,64),256,SCORE_SMEM>>>(gq, gk, gkr, rwb, rrb, gef, gsg, gs);
    softmax_kernel<<<8192,256>>>(gs);

    // attn_vec = P @ V (batched, causal K-truncation); v rounded at B-fragment load
    gemm_tc<64,64,4,2,false,0,false,true,true><<<dim3(1,16,64),256,SM_PV>>>(gs, gv, gav,
        nullptr, nullptr, 1024, 64, 1024, 1024,4096,4096,0,
        16ll*1048576ll, 1048576ll, 1024ll, 64ll, 1024ll, 64ll, 1);

    // o-projection (B transposed, pre-rounded) + residual h (fp32)
    gemm_tc<128,128,4,2,true,2,false,false,false><<<dim3(8,32,1),256,SM_TRB>>>(gav, gwo, gpre,
        nullptr, h, NTOK, DMODEL, DMODEL, 1024,1024,1024,1024, 0,0,0,0,0,0, 0);
    ln_kernel<<<4096,256>>>(gpre, ln1g, ln1b, go1);

    // FF1 (+bias, GELU) and FF2 (+bias, +residual)
    gemm_tc<128,128,4,2,false,1,true,false,true><<<dim3(32,32,1),256,SM_NRM>>>(go1, gw1t, gffh,
        b1, nullptr, NTOK, DFF, DMODEL, 1024,4096,4096,0, 0,0,0,0,0,0, 0);
    gemm_tc<128,128,4,2,false,3,false,false,false><<<dim3(8,32,1),256,SM_NRM>>>(gffh, gw2t, gp2,
        b2, go1, NTOK, DMODEL, DFF, 4096,1024,1024,1024, 0,0,0,0,0,0, 0);
    ln_kernel<<<4096,256>>>(gp2, ln2g, ln2b, out);
}